// round 2
// baseline (speedup 1.0000x reference)
#include <cuda_runtime.h>

// Precomputed Pauli coefficients n_q = (nx, ny, nz) of U_q^dag Z U_q, per qubit.
__device__ __align__(16) float g_n[12];

__global__ void vqc_prep(const float* __restrict__ w) {
    int q = threadIdx.x;
    if (q < 4) {
        float th = w[q * 3 + 0];
        float lm = w[q * 3 + 2];
        float st, ct, sl, cl;
        sincosf(th, &st, &ct);
        sincosf(lm, &sl, &cl);
        g_n[q * 3 + 0] = -st * cl;  // nx
        g_n[q * 3 + 1] =  st * sl;  // ny
        g_n[q * 3 + 2] =  ct;       // nz
    }
}

// Compute one circuit's 4 expectation values from 12 encoding angles.
__device__ __forceinline__ float4 vqc_one(const float4& e0, const float4& e1,
                                          const float4& e2,
                                          const float4& n0, const float4& n1,
                                          const float4& n2) {
    float t[12] = {e0.x, e0.y, e0.z, e0.w,
                   e1.x, e1.y, e1.z, e1.w,
                   e2.x, e2.y, e2.z, e2.w};

    float x[4], y[4], z[4];
#pragma unroll
    for (int q = 0; q < 4; q++) {
        float s0, c0, s1, c1, s2, c2;
        __sincosf(t[3 * q + 0], &s0, &c0);
        __sincosf(t[3 * q + 1], &s1, &c1);
        __sincosf(t[3 * q + 2], &s2, &c2);
        float cc = c0 * c1;
        x[q] = cc * c2 - s0 * s2;
        y[q] = cc * s2 + s0 * c2;
        z[q] = -c0 * s1;
    }

    float z01   = z[0] * z[1];
    float z23   = z[2] * z[3];
    float z012  = z01 * z[2];
    float z123  = z[1] * z23;
    float z0123 = z01 * z23;
    float x01   = x[0] * x[1];

    float4 o;
    o.x = n0.x * x01           + n0.y * (x[0] * y[1] * z23)         + n0.z * z123;
    o.y = n0.w * (x[1] * x[2]) + n1.x * (z[0] * y[1] * x[2])        + n1.y * z01;
    o.z = n1.z * (x[2] * x[3]) + n1.w * (z01 * y[2] * x[3])         + n2.x * z012;
    o.w = n2.y * (x01 * x[3])  - n2.z * (y[0] * y[1] * z[2] * y[3]) + n2.w * z0123;
    return o;
}

__global__ __launch_bounds__(256) void vqc_main(const float4* __restrict__ enc,
                                                float4* __restrict__ out,
                                                int B) {
    int i0 = (blockIdx.x * blockDim.x + threadIdx.x) * 2;
    if (i0 >= B) return;

    // Front-load all 6 float4 loads (2 items x 3 vectors) -> MLP=6 per thread.
    float4 e0 = enc[3 * i0 + 0];
    float4 e1 = enc[3 * i0 + 1];
    float4 e2 = enc[3 * i0 + 2];
    float4 e3 = enc[3 * i0 + 3];
    float4 e4 = enc[3 * i0 + 4];
    float4 e5 = enc[3 * i0 + 5];

    const float4* n4 = (const float4*)g_n;
    float4 n0 = n4[0];
    float4 n1 = n4[1];
    float4 n2 = n4[2];

    float4 o0 = vqc_one(e0, e1, e2, n0, n1, n2);
    float4 o1 = vqc_one(e3, e4, e5, n0, n1, n2);

    // Streamed output, never re-read: evict-first.
    __stcs(&out[i0 + 0], o0);
    if (i0 + 1 < B) __stcs(&out[i0 + 1], o1);
}

extern "C" void kernel_launch(void* const* d_in, const int* in_sizes, int n_in,
                              void* d_out, int out_size) {
    int ei = 0, wi = 1;
    if (n_in >= 2 && in_sizes[0] < in_sizes[1]) { ei = 1; wi = 0; }
    const float* enc = (const float*)d_in[ei];
    const float* w   = (const float*)d_in[wi];
    int B = in_sizes[ei] / 12;

    vqc_prep<<<1, 32>>>(w);

    const int threads = 256;
    const int items_per_block = threads * 2;
    int blocks = (B + items_per_block - 1) / items_per_block;
    vqc_main<<<blocks, threads>>>((const float4*)enc, (float4*)d_out, B);
}

// round 4
// speedup vs baseline: 1.1517x; 1.1517x over previous
#include <cuda_runtime.h>
#include <cstdint>

// Precomputed Pauli coefficients n_q = (nx, ny, nz) of U_q^dag Z U_q, per qubit.
__device__ __align__(16) float g_n[12];

__global__ void vqc_prep(const float* __restrict__ w) {
    int q = threadIdx.x;
    if (q < 4) {
        float th = w[q * 3 + 0];
        float lm = w[q * 3 + 2];
        float st, ct, sl, cl;
        sincosf(th, &st, &ct);
        sincosf(lm, &sl, &cl);
        g_n[q * 3 + 0] = -st * cl;  // nx
        g_n[q * 3 + 1] =  st * sl;  // ny
        g_n[q * 3 + 2] =  ct;       // nz
    }
}

__device__ __forceinline__ void cp16(unsigned int saddr, const void* gptr) {
    // 16B global->shared async copy, L1-bypass (cg): no register held, no L1 fill.
    asm volatile("cp.async.cg.shared.global [%0], [%1], 16;" :: "r"(saddr), "l"(gptr));
}

__device__ __forceinline__ float4 vqc_one(float4 e0, float4 e1, float4 e2,
                                          float4 n0, float4 n1, float4 n2) {
    float t[12] = {e0.x, e0.y, e0.z, e0.w,
                   e1.x, e1.y, e1.z, e1.w,
                   e2.x, e2.y, e2.z, e2.w};
    float x[4], y[4], z[4];
#pragma unroll
    for (int q = 0; q < 4; q++) {
        float s0, c0, s1, c1, s2, c2;
        __sincosf(t[3 * q + 0], &s0, &c0);
        __sincosf(t[3 * q + 1], &s1, &c1);
        __sincosf(t[3 * q + 2], &s2, &c2);
        float cc = c0 * c1;
        x[q] = cc * c2 - s0 * s2;
        y[q] = cc * s2 + s0 * c2;
        z[q] = -c0 * s1;
    }
    float z01   = z[0] * z[1];
    float z23   = z[2] * z[3];
    float z012  = z01 * z[2];
    float z123  = z[1] * z23;
    float z0123 = z01 * z23;
    float x01   = x[0] * x[1];

    float4 o;
    o.x = n0.x * x01           + n0.y * (x[0] * y[1] * z23)         + n0.z * z123;
    o.y = n0.w * (x[1] * x[2]) + n1.x * (z[0] * y[1] * x[2])        + n1.y * z01;
    o.z = n1.z * (x[2] * x[3]) + n1.w * (z01 * y[2] * x[3])         + n2.x * z012;
    o.w = n2.y * (x01 * x[3])  - n2.z * (y[0] * y[1] * z[2] * y[3]) + n2.w * z0123;
    return o;
}

// 256 threads/block, 2 tiles of 256 items each, double-buffered cp.async.
__global__ __launch_bounds__(256, 8) void vqc_main(const float4* __restrict__ enc,
                                                   float4* __restrict__ out,
                                                   int B) {
    __shared__ float4 buf[2][768];  // 2 tiles x 256 items x 3 float4 = 24 KB

    const int t = threadIdx.x;
    const int tile0 = blockIdx.x * 2;
    const int nvec = B * 3;  // total float4 count of enc

    // Fire all 6 async copies up-front: deep MLP, zero register residency.
#pragma unroll
    for (int tt = 0; tt < 2; tt++) {
        int vbase = (tile0 + tt) * 768;
#pragma unroll
        for (int k = 0; k < 3; k++) {
            int idx = k * 256 + t;
            if (vbase + idx < nvec) {
                unsigned int saddr =
                    (unsigned int)__cvta_generic_to_shared(&buf[tt][idx]);
                cp16(saddr, enc + vbase + idx);
            }
        }
        asm volatile("cp.async.commit_group;" ::: "memory");
    }

    const float4* n4 = (const float4*)g_n;
    float4 n0 = n4[0], n1 = n4[1], n2 = n4[2];

    // Tile 0 ready (group 1 still in flight).
    asm volatile("cp.async.wait_group 1;" ::: "memory");
    __syncthreads();

#pragma unroll
    for (int tt = 0; tt < 2; tt++) {
        if (tt == 1) {
            asm volatile("cp.async.wait_group 0;" ::: "memory");
            __syncthreads();
        }
        int item = (tile0 + tt) * 256 + t;
        if (item < B) {
            float4 e0 = buf[tt][3 * t + 0];
            float4 e1 = buf[tt][3 * t + 1];
            float4 e2 = buf[tt][3 * t + 2];
            float4 o = vqc_one(e0, e1, e2, n0, n1, n2);
            __stcs(&out[item], o);  // streamed, never re-read
        }
    }
}

extern "C" void kernel_launch(void* const* d_in, const int* in_sizes, int n_in,
                              void* d_out, int out_size) {
    int ei = 0, wi = 1;
    if (n_in >= 2 && in_sizes[0] < in_sizes[1]) { ei = 1; wi = 0; }
    const float* enc = (const float*)d_in[ei];
    const float* w   = (const float*)d_in[wi];
    int B = in_sizes[ei] / 12;

    vqc_prep<<<1, 32>>>(w);

    const int items_per_block = 512;
    int blocks = (B + items_per_block - 1) / items_per_block;
    vqc_main<<<blocks, 256>>>((const float4*)enc, (float4*)d_out, B);
}

// round 5
// speedup vs baseline: 1.1604x; 1.0075x over previous
#include <cuda_runtime.h>

__device__ __forceinline__ float4 vqc_one(float4 e0, float4 e1, float4 e2,
                                          float4 n0, float4 n1, float4 n2) {
    float t[12] = {e0.x, e0.y, e0.z, e0.w,
                   e1.x, e1.y, e1.z, e1.w,
                   e2.x, e2.y, e2.z, e2.w};
    float x[4], y[4], z[4];
#pragma unroll
    for (int q = 0; q < 4; q++) {
        float s0, c0, s1, c1, s2, c2;
        __sincosf(t[3 * q + 0], &s0, &c0);
        __sincosf(t[3 * q + 1], &s1, &c1);
        __sincosf(t[3 * q + 2], &s2, &c2);
        float cc = c0 * c1;
        x[q] = cc * c2 - s0 * s2;
        y[q] = cc * s2 + s0 * c2;
        z[q] = -c0 * s1;
    }
    float z01   = z[0] * z[1];
    float z23   = z[2] * z[3];
    float z012  = z01 * z[2];
    float z123  = z[1] * z23;
    float z0123 = z01 * z23;
    float x01   = x[0] * x[1];

    float4 o;
    o.x = n0.x * x01           + n0.y * (x[0] * y[1] * z23)         + n0.z * z123;
    o.y = n0.w * (x[1] * x[2]) + n1.x * (z[0] * y[1] * x[2])        + n1.y * z01;
    o.z = n1.z * (x[2] * x[3]) + n1.w * (z01 * y[2] * x[3])         + n2.x * z012;
    o.w = n2.y * (x01 * x[3])  - n2.z * (y[0] * y[1] * z[2] * y[3]) + n2.w * z0123;
    return o;
}

__global__ __launch_bounds__(256) void vqc_fused(const float4* __restrict__ enc,
                                                 const float* __restrict__ w,
                                                 float4* __restrict__ out,
                                                 int B) {
    // Per-block computation of the observable coefficients (replaces prep kernel).
    __shared__ __align__(16) float sn[12];
    if (threadIdx.x < 4) {
        int q = threadIdx.x;
        float th = w[q * 3 + 0];
        float lm = w[q * 3 + 2];
        float st, ct, sl, cl;
        sincosf(th, &st, &ct);
        sincosf(lm, &sl, &cl);
        sn[q * 3 + 0] = -st * cl;  // nx
        sn[q * 3 + 1] =  st * sl;  // ny
        sn[q * 3 + 2] =  ct;       // nz
    }
    __syncthreads();
    const float4* n4 = (const float4*)sn;
    float4 n0 = n4[0], n1 = n4[1], n2 = n4[2];

    const int stride = gridDim.x * blockDim.x;
    int i = blockIdx.x * blockDim.x + threadIdx.x;

    // Persistent grid-stride: full occupancy for the whole run, no wave tail.
    for (; i < B; i += stride) {
        const float4* p = enc + 3 * i;
        float4 e0 = __ldcs(p + 0);   // read-once stream: evict-first
        float4 e1 = __ldcs(p + 1);
        float4 e2 = __ldcs(p + 2);
        float4 o = vqc_one(e0, e1, e2, n0, n1, n2);
        __stcs(&out[i], o);          // write-once stream: evict-first
    }
}

extern "C" void kernel_launch(void* const* d_in, const int* in_sizes, int n_in,
                              void* d_out, int out_size) {
    int ei = 0, wi = 1;
    if (n_in >= 2 && in_sizes[0] < in_sizes[1]) { ei = 1; wi = 0; }
    const float* enc = (const float*)d_in[ei];
    const float* w   = (const float*)d_in[wi];
    int B = in_sizes[ei] / 12;

    const int threads = 256;
    // Persistent grid: at most ~8 blocks/SM on 152 SMs; never more than needed.
    int max_blocks = 152 * 8;
    int need = (B + threads - 1) / threads;
    int blocks = need < max_blocks ? need : max_blocks;

    vqc_fused<<<blocks, threads>>>((const float4*)enc, w, (float4*)d_out, B);
}